// round 1
// baseline (speedup 1.0000x reference)
#include <cuda_runtime.h>

// CRF loss: T=512, B=1024, K=48. Inputs: feats(T,B,K) f32, transitions(K,K) f32,
// tags(B,T) i32, lengths(B,) i32. Output: scalar f32.
//
// Strategy: one block per batch element. Log-semiring matvec converted to
// linear-space matvec with precomputed exp(trans) held in registers
// (48 floats/thread). Per step: warp+smem max reduction, K exps, 48 FMAs per
// thread from broadcast smem reads, one log. Loop runs only lengths[b] steps.

#define TT 512
#define BB 1024
#define KK 48
#define START_TAG 46
#define STOP_TAG  47
#define NEGV (-10000.0f)

__device__ float g_partial[BB];

__global__ void __launch_bounds__(64, 8) crf_kernel(
    const float* __restrict__ feats,
    const float* __restrict__ trans,
    const int*   __restrict__ tags,
    const int*   __restrict__ lengths)
{
    __shared__ __align__(16) float s_ea[2][64];
    __shared__ float s_wmax[2][2];
    __shared__ float s_red[2];
    __shared__ float s_trans[KK * KK];

    const int b    = blockIdx.x;
    const int tid  = threadIdx.x;
    const int lane = tid & 31;
    const int warp = tid >> 5;
    const bool active = (tid < KK);
    const int len = lengths[b];

    // raw transitions in smem (gold lookups + STOP row)
    for (int i = tid; i < KK * KK; i += 64) s_trans[i] = trans[i];

    // per-thread exp(trans[j, :]) row in registers
    float et[KK];
    if (active) {
        #pragma unroll
        for (int i = 0; i < KK; i++)
            et[i] = __expf(trans[tid * KK + i]);   // exp(-10000) == 0.0f
    }
    float alpha = (tid == START_TAG) ? 0.0f : NEGV;

    __syncthreads();

    const float* fb = feats + b * KK;              // feats[t*B*K + b*K + j]
    float fcur = active ? __ldg(fb + tid) : 0.0f;  // t = 0 (len >= 1 always)

    int buf = 0;
    for (int t = 0; t < len; t++) {
        // software-pipeline next feat load
        float fnext = 0.0f;
        if (active && (t + 1 < len))
            fnext = __ldg(fb + (size_t)(t + 1) * (BB * KK) + tid);

        // global max of alpha (warp shfl + cross-warp via smem)
        float m = alpha;
        #pragma unroll
        for (int o = 16; o; o >>= 1) m = fmaxf(m, __shfl_xor_sync(~0u, m, o));
        if (lane == 0) s_wmax[buf][warp] = m;
        __syncthreads();
        m = fmaxf(s_wmax[buf][0], s_wmax[buf][1]);

        // exp-shifted alpha into smem (double-buffered)
        s_ea[buf][tid] = active ? __expf(alpha - m) : 0.0f;
        __syncthreads();

        if (active) {
            const float4* ev = (const float4*)(s_ea[buf]);
            float s0 = 0.f, s1 = 0.f, s2 = 0.f, s3 = 0.f;
            #pragma unroll
            for (int q = 0; q < KK / 4; q++) {
                float4 e = ev[q];                  // broadcast, conflict-free
                s0 = fmaf(e.x, et[4*q + 0], s0);
                s1 = fmaf(e.y, et[4*q + 1], s1);
                s2 = fmaf(e.z, et[4*q + 2], s2);
                s3 = fmaf(e.w, et[4*q + 3], s3);
            }
            alpha = fcur + m + __logf((s0 + s1) + (s2 + s3));
        }
        fcur = fnext;
        buf ^= 1;
    }
    __syncthreads();

    // log_z = logsumexp_j(alpha_j + trans[STOP, j])
    float v = active ? alpha + s_trans[STOP_TAG * KK + tid] : NEGV;
    float mz = v;
    #pragma unroll
    for (int o = 16; o; o >>= 1) mz = fmaxf(mz, __shfl_xor_sync(~0u, mz, o));
    if (lane == 0) s_wmax[0][warp] = mz;
    __syncthreads();
    mz = fmaxf(s_wmax[0][0], s_wmax[0][1]);
    float ez = active ? __expf(v - mz) : 0.0f;
    #pragma unroll
    for (int o = 16; o; o >>= 1) ez += __shfl_xor_sync(~0u, ez, o);
    if (lane == 0) s_red[warp] = ez;
    __syncthreads();
    float logz = mz + __logf(s_red[0] + s_red[1]);
    __syncthreads();

    // gold score: parallel over t, block reduce
    const int* tg = tags + b * TT;
    float g = 0.0f;
    for (int t = tid; t < len; t += 64) {
        int nxt = __ldg(tg + t);
        int prv = (t == 0) ? START_TAG : __ldg(tg + t - 1);
        g += s_trans[nxt * KK + prv] + __ldg(fb + (size_t)t * (BB * KK) + nxt);
    }
    #pragma unroll
    for (int o = 16; o; o >>= 1) g += __shfl_xor_sync(~0u, g, o);
    if (lane == 0) s_red[warp] = g;
    __syncthreads();

    if (tid == 0) {
        float gold = s_red[0] + s_red[1]
                   + s_trans[STOP_TAG * KK + __ldg(tg + len - 1)];
        g_partial[b] = logz - gold;
    }
}

// Deterministic fixed-order tree reduction (no float atomics).
__global__ void reduce_kernel(float* __restrict__ out) {
    __shared__ float s[512];
    int tid = threadIdx.x;
    s[tid] = g_partial[tid] + g_partial[tid + 512];
    __syncthreads();
    #pragma unroll
    for (int o = 256; o; o >>= 1) {
        if (tid < o) s[tid] += s[tid + o];
        __syncthreads();
    }
    if (tid == 0) out[0] = s[0];
}

extern "C" void kernel_launch(void* const* d_in, const int* in_sizes, int n_in,
                              void* d_out, int out_size) {
    const float* feats   = (const float*)d_in[0];
    const float* trans   = (const float*)d_in[1];
    const int*   tags    = (const int*)d_in[2];
    const int*   lengths = (const int*)d_in[3];
    crf_kernel<<<BB, 64>>>(feats, trans, tags, lengths);
    reduce_kernel<<<1, 512>>>((float*)d_out);
}